// round 13
// baseline (speedup 1.0000x reference)
#include <cuda_runtime.h>
#include <cuda_bf16.h>
#include <stdint.h>

// Problem constants (reference: N=2048, NUM_COLORS=16, x in [0,16))
#define NN     2048
#define NSH    11            // log2(NN)
#define NC     16
#define CELLS  (NN*NN)       // 4,194,304
#define NBLK   1024          // slow-path scan blocks (4096 cells each)

// dtype modes
#define MODE_I64  0
#define MODE_I32  1
#define MODE_F32  2
#define MODE_F64  3
#define MODE_BF16 4

// ---------------- scratch (static __device__ arrays; no allocs) ----------------
static __device__ unsigned char      g_x8[CELLS];                 // 4 MB
static __device__ int                g_rowhist[NN*NC];
static __device__ int                g_colhist[NN*NC];
static __device__ unsigned long long g_hash[2*NN];
static __device__ int                g_rclass[NN];
static __device__ int                g_cclass[NN];
static __device__ unsigned int       g_table[NC*CELLS];           // 256 MB (slow path only)
static __device__ int                g_scan[CELLS];
static __device__ int                g_bsums[NBLK];
static __device__ unsigned int       g_barc[8];                   // k_slow phase barriers
static __device__ unsigned int       g_ccnt[8];                   // colhist finisher counters
static __device__ int                g_fast;

// ---------------- helpers ----------------
__device__ __forceinline__ int hw_ok(unsigned h) {
    return h == 0u || (h >= 0x3F80u && h <= 0x4170u);
}
// Per-block dtype detection over input words [0,512). L2-hot, ~trivial.
__device__ int detect_mode(const unsigned* __restrict__ x, int t, int* bad) {
    if (t < 5) bad[t] = 0;
    __syncthreads();
    unsigned w0 = x[2*t], w1 = x[2*t+1];
    if (!(w1 == 0u && w0 < 16u))                         bad[MODE_I64] = 1;
    if (!(w0 < 16u && w1 < 16u))                         bad[MODE_I32] = 1;
    int f0 = (w0 == 0u) || (((w0 & 0xFFFFu) == 0u) && hw_ok(w0 >> 16));
    int f1 = (w1 == 0u) || (((w1 & 0xFFFFu) == 0u) && hw_ok(w1 >> 16));
    if (!(f0 && f1))                                     bad[MODE_F32] = 1;
    if (!(w0 == 0u && (w1 == 0u || (w1 >= 0x3FF00000u && w1 <= 0x402E0000u))))
                                                         bad[MODE_F64] = 1;
    if (!(hw_ok(w0 & 0xFFFFu) && hw_ok(w0 >> 16) &&
          hw_ok(w1 & 0xFFFFu) && hw_ok(w1 >> 16)))       bad[MODE_BF16] = 1;
    __syncthreads();
    if      (!bad[MODE_I64])  return MODE_I64;
    else if (!bad[MODE_I32])  return MODE_I32;
    else if (!bad[MODE_F64])  return MODE_F64;
    else if (!bad[MODE_F32])  return MODE_F32;
    else if (!bad[MODE_BF16]) return MODE_BF16;
    return MODE_I32;
}
__device__ __forceinline__ unsigned long long fnv16(const int* h) {
    unsigned long long hv = 1469598103934665603ULL;
#pragma unroll
    for (int c = 0; c < NC; c++) {
        hv ^= (unsigned long long)(unsigned)h[c];
        hv *= 1099511628211ULL;
    }
    return hv;
}

// ---------------- k_convert: detect + decode + ROW HIST + row hash + glue ----
// One block == one row (256 threads x 8 cells = 2048 cells).
__global__ void k_convert(const void* __restrict__ xv) {
    __shared__ int bad[5];
    __shared__ int wb[8*NC];
    __shared__ int rh[NC];
    int t = threadIdx.x;
    int m = detect_mode((const unsigned*)xv, t, bad);
    int row = blockIdx.x;
    int gid = row*256 + t;
    // init glue (spread over early threads)
    if (gid == 0) g_fast = 1;
    if (gid < 8)  { g_barc[gid] = 0; g_ccnt[gid] = 0; }
    if (gid < NN*NC) g_colhist[gid] = 0;
    if (t < 8*NC) wb[t] = 0;
    __syncthreads();
    // decode 8 cells, branch hoisted out of the element loop
    int base = gid*8;
    unsigned v[8];
    if (m == MODE_I32) {
        const int4* p = (const int4*)((const int*)xv + base);
        int4 a = p[0], b = p[1];
        v[0]=(unsigned)a.x&0xFu; v[1]=(unsigned)a.y&0xFu; v[2]=(unsigned)a.z&0xFu; v[3]=(unsigned)a.w&0xFu;
        v[4]=(unsigned)b.x&0xFu; v[5]=(unsigned)b.y&0xFu; v[6]=(unsigned)b.z&0xFu; v[7]=(unsigned)b.w&0xFu;
    } else if (m == MODE_F32) {
        const float4* p = (const float4*)((const float*)xv + base);
        float4 a = p[0], b = p[1];
        v[0]=(unsigned)(int)a.x&0xFu; v[1]=(unsigned)(int)a.y&0xFu; v[2]=(unsigned)(int)a.z&0xFu; v[3]=(unsigned)(int)a.w&0xFu;
        v[4]=(unsigned)(int)b.x&0xFu; v[5]=(unsigned)(int)b.y&0xFu; v[6]=(unsigned)(int)b.z&0xFu; v[7]=(unsigned)(int)b.w&0xFu;
    } else if (m == MODE_I64) {
        const unsigned* p = (const unsigned*)xv;
#pragma unroll
        for (int e = 0; e < 8; e++) v[e] = p[2*(base+e)] & 0xFu;
    } else if (m == MODE_F64) {
        const double* p = (const double*)xv;
#pragma unroll
        for (int e = 0; e < 8; e++) v[e] = (unsigned)(int)p[base+e] & 0xFu;
    } else { // BF16
        const unsigned short* p = (const unsigned short*)xv;
#pragma unroll
        for (int e = 0; e < 8; e++)
            v[e] = (unsigned)(int)__uint_as_float((unsigned)p[base+e] << 16) & 0xFu;
    }
    unsigned long long w = 0;
#pragma unroll
    for (int e = 0; e < 8; e++) w |= ((unsigned long long)v[e]) << (8*e);
    ((unsigned long long*)g_x8)[gid] = w;
    // row histogram (R9 body, values already in registers)
    int wp = (t >> 5) * NC;
#pragma unroll
    for (int e = 0; e < 8; e++)
        atomicAdd(&wb[wp + (int)v[e]], 1);
    __syncthreads();
    if (t < NC) {
        int s = 0;
#pragma unroll
        for (int k = 0; k < 8; k++) s += wb[k*NC + t];
        g_rowhist[row*NC + t] = s;
        rh[t] = s;
    }
    __syncthreads();
    if (t == 0) g_hash[row] = fnv16(rh);
}

// ---------------- k_colhist (R9 body) + fused col-hash finisher ----------------
// grid (8, 16): x = column group (256 cols), y = row chunk (128 rows).
// The 16th finishing block of a column group computes that group's hashes.
__global__ void k_colhist() {
    __shared__ unsigned char sb[NC*256];
    __shared__ int fin;
    int t = threadIdx.x;
#pragma unroll
    for (int c = 0; c < NC; c++) sb[c*256 + t] = 0;
    __syncthreads();
    int j  = blockIdx.x*256 + t;
    int r0 = blockIdx.y * (NN/16);
    for (int r = r0; r < r0 + NN/16; r++) {
        int v = g_x8[r*NN + j];
        sb[v*256 + t]++;
    }
#pragma unroll
    for (int c = 0; c < NC; c++) {
        int cnt = sb[c*256 + t];
        if (cnt) atomicAdd(&g_colhist[j*NC + c], cnt);
    }
    __threadfence();
    __syncthreads();
    if (t == 0) {
        unsigned old = atomicAdd(&g_ccnt[blockIdx.x], 1u);
        fin = (old == 15u);
    }
    __syncthreads();
    if (fin) {
        __threadfence();
        g_hash[NN + j] = fnv16(&g_colhist[j*NC]);
    }
}

// ---------------- k_class (+ fast-path check) ----------------
__global__ void k_class() {
    int i = blockIdx.x, isCol = blockIdx.y, t = threadIdx.x;
    const unsigned long long* H = g_hash + isCol*NN;
    const int* hist = isCol ? g_colhist : g_rowhist;
    unsigned long long hi = H[i];
    int best = i;
    for (int j = t; j < i; j += 256) {
        if (H[j] == hi) {
            bool eq = true;
#pragma unroll
            for (int c = 0; c < NC; c++) eq = eq && (hist[j*NC + c] == hist[i*NC + c]);
            if (eq && j < best) best = j;
        }
    }
    __shared__ int red[256];
    red[t] = best;
    __syncthreads();
    for (int s = 128; s; s >>= 1) {
        if (t < s) red[t] = min(red[t], red[t+s]);
        __syncthreads();
    }
    if (t == 0) {
        (isCol ? g_cclass : g_rclass)[i] = red[0];
        if (red[0] != i) g_fast = 0;
    }
}

__device__ __forceinline__ unsigned cell_key(int p) {
    int i = p >> NSH, j = p & (NN-1);
    return ((unsigned)g_x8[p] << 22) | ((unsigned)g_rclass[i] << NSH) | (unsigned)g_cclass[j];
}

// ---------------- k_slow: full fallback in ONE kernel ----------------
// 1024 blocks x 256 threads — fully resident, counter barriers safe.
// Counters zeroed by k_convert. Fast path: immediate return.
__device__ __forceinline__ void gbar(int ph) {
    __syncthreads();
    if (threadIdx.x == 0) {
        atomicAdd(&g_barc[ph], 1u);
        while (*(volatile unsigned*)&g_barc[ph] < (unsigned)NBLK) { }
    }
    __syncthreads();
}
__global__ void __launch_bounds__(256) k_slow() {
    if (g_fast) return;
    int blk = blockIdx.x, t = threadIdx.x;
    int cbase = blk*4096;
    // phase 0: reset touched table slots (benign duplicate stores)
    for (int p = cbase + t; p < cbase + 4096; p += 256)
        g_table[cell_key(p)] = 0xFFFFFFFFu;
    gbar(0);
    // phase 1: min row-major index per key
    for (int p = cbase + t; p < cbase + 4096; p += 256)
        atomicMin(&g_table[cell_key(p)], (unsigned)p);
    gbar(1);
    // phase 2: first-occurrence flags + per-block exclusive scan
    {
        int base = cbase + t*16;
        int f[16], s = 0;
#pragma unroll
        for (int e = 0; e < 16; e++) {
            int p = base + e;
            f[e] = (g_table[cell_key(p)] == (unsigned)p);
            s += f[e];
        }
        int lane = t & 31, warp = t >> 5;
        int v = s;
#pragma unroll
        for (int o = 1; o < 32; o <<= 1) {
            int nv = __shfl_up_sync(0xffffffffu, v, o);
            if (lane >= o) v += nv;
        }
        __shared__ int ws[8], wo[8];
        if (lane == 31) ws[warp] = v;
        __syncthreads();
        if (t < 8) {
            int w = ws[t];
#pragma unroll
            for (int o = 1; o < 8; o <<= 1) {
                int nv = __shfl_up_sync(0xffu, w, o);
                if (t >= o) w += nv;
            }
            wo[t] = w;
        }
        __syncthreads();
        int ex = (v - s) + (warp ? wo[warp-1] : 0);
        if (t == 255) g_bsums[blk] = wo[7];
        int run = ex;
#pragma unroll
        for (int e = 0; e < 16; e++) { g_scan[base + e] = run; run += f[e]; }
    }
    gbar(2);
    // phase 3: exclusive scan of block sums (block 0, serial — slow path only)
    if (blk == 0 && t == 0) {
        int acc = 0;
        for (int b = 0; b < NBLK; b++) {
            int s = g_bsums[b];
            g_bsums[b] = acc;
            acc += s;
        }
        __threadfence();
        atomicAdd(&g_barc[3], 1u);
    }
}

// ---------------- k_out ----------------
// Fast path: out[p] = p. Slow path: rank lookup.
__global__ void k_out(float* __restrict__ out) {
    int t = blockIdx.x*blockDim.x + threadIdx.x;   // 0 .. CELLS/8-1
    int base = t*8;
    float4 r0, r1;
    if (g_fast) {
        r0 = make_float4((float)base,     (float)(base+1), (float)(base+2), (float)(base+3));
        r1 = make_float4((float)(base+4), (float)(base+5), (float)(base+6), (float)(base+7));
    } else {
        float v[8];
#pragma unroll
        for (int e = 0; e < 8; e++) {
            unsigned q = g_table[cell_key(base + e)];
            v[e] = (float)(g_scan[q] + g_bsums[q >> 12]);
        }
        r0 = make_float4(v[0], v[1], v[2], v[3]);
        r1 = make_float4(v[4], v[5], v[6], v[7]);
    }
    float4* o = (float4*)(out + base);
    o[0] = r0;
    o[1] = r1;
}

// ---------------- launch (5 kernels) ----------------
extern "C" void kernel_launch(void* const* d_in, const int* in_sizes, int n_in,
                              void* d_out, int out_size) {
    const void* x = d_in[0];
    (void)in_sizes; (void)n_in; (void)out_size;

    k_convert <<<NN, 256>>>(x);
    k_colhist <<<dim3(8, 16), 256>>>();
    k_class   <<<dim3(NN, 2), 256>>>();
    k_slow    <<<NBLK, 256>>>();
    k_out     <<<CELLS/8/256, 256>>>((float*)d_out);
}